// round 3
// baseline (speedup 1.0000x reference)
#include <cuda_runtime.h>

#define N_EMB   512
#define EMB_D   64
#define HWSZ    4096
#define NTOK    131072
#define TPB     512
#define NCHUNK  (NTOK / TPB)        // 256 chunks of 512 tokens
#define GRID_A  148

// Output packing (float32, reference tuple order)
#define OFF_RES 0ULL
#define OFF_ARG 8388608ULL
#define OFF_W   8519680ULL
#define OFF_CS  8552448ULL
#define OFF_EA  8552960ULL

#define SMEM_BYTES ((N_EMB * EMB_D + N_EMB) * 4)   // 133120 B

__device__ float g_hist[N_EMB];
__device__ float g_esum[EMB_D * N_EMB];
__device__ float g_ww[N_EMB];
__device__ float g_wt[N_EMB * EMB_D];   // weight transposed: [j][d]
__device__ unsigned int g_work;
__device__ unsigned int g_done;

__device__ __forceinline__ unsigned long long ffma2(unsigned long long a,
                                                    unsigned long long b,
                                                    unsigned long long c) {
    unsigned long long d;
    asm("fma.rn.f32x2 %0, %1, %2, %3;" : "=l"(d) : "l"(a), "l"(b), "l"(c));
    return d;
}

__device__ __forceinline__ unsigned long long fadd2(unsigned long long a,
                                                    unsigned long long b) {
    unsigned long long d;
    asm("add.rn.f32x2 %0, %1, %2;" : "=l"(d) : "l"(a), "l"(b));
    return d;
}

__device__ __forceinline__ unsigned long long pack2(float lo, float hi) {
    unsigned long long r;
    asm("mov.b64 %0, {%1, %2};" : "=l"(r)
        : "r"(__float_as_uint(lo)), "r"(__float_as_uint(hi)));
    return r;
}

__device__ __forceinline__ void unpack2(unsigned long long v, float& lo, float& hi) {
    unsigned int a, b;
    asm("mov.b64 {%0, %1}, %2;" : "=r"(a), "=r"(b) : "l"(v));
    lo = __uint_as_float(a);
    hi = __uint_as_float(b);
}

// ---------------------------------------------------------------------------
// prep: zero scratch, transpose weight, precompute ||w_j||^2, reset counters
// ---------------------------------------------------------------------------
__global__ void prep_kernel(const float* __restrict__ w) {
    int idx = blockIdx.x * blockDim.x + threadIdx.x;
    if (idx == 0) { g_work = 0u; g_done = 0u; }
    if (idx < EMB_D * N_EMB) {
        g_esum[idx] = 0.0f;
        int j = idx >> 6;
        int d = idx & 63;
        g_wt[idx] = w[d * N_EMB + j];
    }
    if (idx < N_EMB) {
        g_hist[idx] = 0.0f;
        float s = 0.0f;
        #pragma unroll
        for (int d = 0; d < EMB_D; d++) {
            float v = w[d * N_EMB + idx];
            s = __fadd_rn(s, __fmul_rn(v, v));
        }
        g_ww[idx] = s;
    }
}

// ---------------------------------------------------------------------------
// assign: persistent CTAs (148 x 512 thr), work-steal over 256 chunks.
// Hot loop: LDS.128 broadcast + FFMA2, 4 codewords x 2 accumulators.
// Last CTA to finish performs the EMA finalize (merged kernel).
// ---------------------------------------------------------------------------
extern __shared__ float smem_dyn[];

__global__ void __launch_bounds__(TPB, 1)
assign_kernel(const float* __restrict__ x,
              const float* __restrict__ cs_in,
              const float* __restrict__ ea_in,
              float* __restrict__ out) {
    float* w_s  = smem_dyn;                     // [512][64] j-major
    float* ww_s = smem_dyn + N_EMB * EMB_D;     // [512]
    __shared__ int s_chunk;
    __shared__ unsigned int s_rank;

    int tid = threadIdx.x;

    // Stage transposed weight once per CTA: coalesced, conflict-free
    {
        const float4* src = (const float4*)g_wt;
        float4* dst = (float4*)w_s;
        #pragma unroll
        for (int i = 0; i < (N_EMB * EMB_D / 4) / TPB; i++)
            dst[i * TPB + tid] = src[i * TPB + tid];
        if (tid < N_EMB) ww_s[tid] = g_ww[tid];
    }

    for (;;) {
        __syncthreads();
        if (tid == 0) s_chunk = (int)atomicAdd(&g_work, 1u);
        __syncthreads();
        int c = s_chunk;
        if (c >= NCHUNK) break;

        int t  = c * TPB + tid;
        int b  = t >> 12;
        int hw = t & (HWSZ - 1);
        const float* xb = x + (size_t)b * EMB_D * HWSZ + hw;

        // Token features -> packed f32x2 (kept in registers)
        unsigned long long xp[EMB_D / 2];
        #pragma unroll
        for (int i = 0; i < EMB_D / 2; i++) {
            float a  = xb[(2 * i)     * HWSZ];
            float cc = xb[(2 * i + 1) * HWSZ];
            xp[i] = pack2(a, cc);
        }

        float best = 3.4e38f;
        int   bi   = 0;

        #pragma unroll 1
        for (int j0 = 0; j0 < N_EMB; j0 += 4) {
            const ulonglong2* r0 = (const ulonglong2*)(w_s + (j0 + 0) * EMB_D);
            const ulonglong2* r1 = (const ulonglong2*)(w_s + (j0 + 1) * EMB_D);
            const ulonglong2* r2 = (const ulonglong2*)(w_s + (j0 + 2) * EMB_D);
            const ulonglong2* r3 = (const ulonglong2*)(w_s + (j0 + 3) * EMB_D);

            unsigned long long a0e = 0ULL, a0o = 0ULL, a1e = 0ULL, a1o = 0ULL;
            unsigned long long a2e = 0ULL, a2o = 0ULL, a3e = 0ULL, a3o = 0ULL;

            #pragma unroll
            for (int q = 0; q < EMB_D / 4; q++) {
                ulonglong2 v0 = r0[q];
                ulonglong2 v1 = r1[q];
                ulonglong2 v2 = r2[q];
                ulonglong2 v3 = r3[q];
                unsigned long long xa = xp[2 * q];
                unsigned long long xc = xp[2 * q + 1];
                a0e = ffma2(xa, v0.x, a0e);  a0o = ffma2(xc, v0.y, a0o);
                a1e = ffma2(xa, v1.x, a1e);  a1o = ffma2(xc, v1.y, a1o);
                a2e = ffma2(xa, v2.x, a2e);  a2o = ffma2(xc, v2.y, a2o);
                a3e = ffma2(xa, v3.x, a3e);  a3o = ffma2(xc, v3.y, a3o);
            }

            float lo, hi;
            unpack2(fadd2(a0e, a0o), lo, hi);
            float d0 = __fmaf_rn(-2.0f, __fadd_rn(lo, hi), ww_s[j0 + 0]);
            unpack2(fadd2(a1e, a1o), lo, hi);
            float d1 = __fmaf_rn(-2.0f, __fadd_rn(lo, hi), ww_s[j0 + 1]);
            unpack2(fadd2(a2e, a2o), lo, hi);
            float d2 = __fmaf_rn(-2.0f, __fadd_rn(lo, hi), ww_s[j0 + 2]);
            unpack2(fadd2(a3e, a3o), lo, hi);
            float d3 = __fmaf_rn(-2.0f, __fadd_rn(lo, hi), ww_s[j0 + 3]);

            // strict < ascending j => first-min tie-break (matches jnp.argmin)
            if (d0 < best) { best = d0; bi = j0 + 0; }
            if (d1 < best) { best = d1; bi = j0 + 1; }
            if (d2 < best) { best = d2; bi = j0 + 2; }
            if (d3 < best) { best = d3; bi = j0 + 3; }
        }

        out[OFF_ARG + (size_t)t] = (float)bi;

        // quantized result from smem codebook (coalesced per d-plane)
        float* ro = out + (size_t)b * EMB_D * HWSZ + hw;
        const float4* wrow = (const float4*)(w_s + bi * EMB_D);
        #pragma unroll
        for (int i = 0; i < EMB_D / 4; i++) {
            float4 v = wrow[i];
            ro[(4 * i + 0) * HWSZ] = v.x;
            ro[(4 * i + 1) * HWSZ] = v.y;
            ro[(4 * i + 2) * HWSZ] = v.z;
            ro[(4 * i + 3) * HWSZ] = v.w;
        }

        // EMA accumulators
        atomicAdd(&g_hist[bi], 1.0f);
        #pragma unroll
        for (int i = 0; i < EMB_D / 2; i++) {
            float lo, hi;
            unpack2(xp[i], lo, hi);
            atomicAdd(&g_esum[(2 * i)     * N_EMB + bi], lo);
            atomicAdd(&g_esum[(2 * i + 1) * N_EMB + bi], hi);
        }
    }

    // ------- merged finalize: last CTA to finish does the EMA update -------
    __threadfence();
    __syncthreads();
    if (tid == 0) s_rank = atomicAdd(&g_done, 1u);
    __syncthreads();
    if (s_rank == GRID_A - 1) {
        float* red = smem_dyn;     // codebook is dead now
        int j = tid;               // TPB == N_EMB == 512

        const float DEC  = 0.99f;
        const float OMD  = (float)(1.0 - 0.99);
        const float EPSF = (float)1e-5;
        const float NEPS = (float)(N_EMB * 1e-5);

        float nidx = g_hist[j];
        if (nidx == 0.0f) nidx = 1.0f;
        float ncs = __fadd_rn(__fmul_rn(DEC, cs_in[j]), __fmul_rn(OMD, nidx));

        __syncthreads();
        red[j] = ncs;
        __syncthreads();
        #pragma unroll
        for (int s = N_EMB / 2; s > 0; s >>= 1) {
            if (j < s) red[j] += red[j + s];
            __syncthreads();
        }
        float n = red[0];

        float csn = __fmul_rn(__fdiv_rn(__fadd_rn(ncs, EPSF),
                                        __fadd_rn(n, NEPS)), n);

        out[OFF_CS + j] = ncs;

        for (int d = 0; d < EMB_D; d++) {
            int idx = d * N_EMB + j;
            float e = __fadd_rn(__fmul_rn(DEC, ea_in[idx]),
                                __fmul_rn(OMD, g_esum[idx]));
            out[OFF_EA + idx] = e;
            out[OFF_W  + idx] = __fdiv_rn(e, csn);
        }
    }
}

// ---------------------------------------------------------------------------
extern "C" void kernel_launch(void* const* d_in, const int* in_sizes, int n_in,
                              void* d_out, int out_size) {
    const float* x  = (const float*)d_in[0];
    const float* w  = (const float*)d_in[1];
    const float* cs = (const float*)d_in[2];
    const float* ea = (const float*)d_in[3];
    float* out = (float*)d_out;

    cudaFuncSetAttribute(assign_kernel,
                         cudaFuncAttributeMaxDynamicSharedMemorySize, SMEM_BYTES);

    prep_kernel<<<128, 256>>>(w);
    assign_kernel<<<GRID_A, TPB, SMEM_BYTES>>>(x, cs, ea, out);
}

// round 4
// speedup vs baseline: 1.7820x; 1.7820x over previous
#include <cuda_runtime.h>

#define N_EMB   512
#define EMB_D   64
#define HWSZ    4096
#define NTOK    131072
#define TPB     256
#define TOKS_PER_CHUNK (TPB * 2)          // T=2 tokens per thread
#define NCHUNK  (NTOK / TOKS_PER_CHUNK)   // 256
#define GRID_A  148

// Output packing (float32, reference tuple order)
#define OFF_RES 0ULL
#define OFF_ARG 8388608ULL
#define OFF_W   8519680ULL
#define OFF_CS  8552448ULL
#define OFF_EA  8552960ULL

#define SMEM_BYTES ((N_EMB * EMB_D + N_EMB) * 4)   // 133120 B

__device__ float g_hist[N_EMB];
__device__ float g_esum[EMB_D * N_EMB];
__device__ float g_ww[N_EMB];
__device__ float g_wt[N_EMB * EMB_D];   // weight transposed: [j][d]
__device__ unsigned int g_work;
__device__ unsigned int g_done;

__device__ __forceinline__ unsigned long long ffma2(unsigned long long a,
                                                    unsigned long long b,
                                                    unsigned long long c) {
    unsigned long long d;
    asm("fma.rn.f32x2 %0, %1, %2, %3;" : "=l"(d) : "l"(a), "l"(b), "l"(c));
    return d;
}

__device__ __forceinline__ unsigned long long fadd2(unsigned long long a,
                                                    unsigned long long b) {
    unsigned long long d;
    asm("add.rn.f32x2 %0, %1, %2;" : "=l"(d) : "l"(a), "l"(b));
    return d;
}

__device__ __forceinline__ unsigned long long pack2(float lo, float hi) {
    unsigned long long r;
    asm("mov.b64 %0, {%1, %2};" : "=l"(r)
        : "r"(__float_as_uint(lo)), "r"(__float_as_uint(hi)));
    return r;
}

__device__ __forceinline__ void unpack2(unsigned long long v, float& lo, float& hi) {
    unsigned int a, b;
    asm("mov.b64 {%0, %1}, %2;" : "=r"(a), "=r"(b) : "l"(v));
    lo = __uint_as_float(a);
    hi = __uint_as_float(b);
}

// ---------------------------------------------------------------------------
// prep: zero scratch, transpose weight, precompute ||w_j||^2, reset counters
// ---------------------------------------------------------------------------
__global__ void prep_kernel(const float* __restrict__ w) {
    int idx = blockIdx.x * blockDim.x + threadIdx.x;
    if (idx == 0) { g_work = 0u; g_done = 0u; }
    if (idx < EMB_D * N_EMB) {
        g_esum[idx] = 0.0f;
        int j = idx >> 6;
        int d = idx & 63;
        g_wt[idx] = w[d * N_EMB + j];
    }
    if (idx < N_EMB) {
        g_hist[idx] = 0.0f;
        float s = 0.0f;
        #pragma unroll
        for (int d = 0; d < EMB_D; d++) {
            float v = w[d * N_EMB + idx];
            s = __fadd_rn(s, __fmul_rn(v, v));
        }
        g_ww[idx] = s;
    }
}

// ---------------------------------------------------------------------------
// assign: persistent CTAs (148 x 256 thr), T=2 tokens/thread, work-steal.
// Hot loop: 2 broadcast LDS.128 -> 8 independent FFMA2 (2 codewords x 2
// tokens x even/odd halves). Codebook staged once per CTA.
// Last CTA performs the EMA finalize.
// ---------------------------------------------------------------------------
extern __shared__ float smem_dyn[];

__global__ void __launch_bounds__(TPB, 1)
assign_kernel(const float* __restrict__ x,
              const float* __restrict__ cs_in,
              const float* __restrict__ ea_in,
              float* __restrict__ out) {
    float* w_s  = smem_dyn;                     // [512][64] j-major
    float* ww_s = smem_dyn + N_EMB * EMB_D;     // [512]
    __shared__ int s_chunk;
    __shared__ unsigned int s_rank;

    int tid = threadIdx.x;

    // Stage transposed weight once per CTA: coalesced, conflict-free
    {
        const float4* src = (const float4*)g_wt;
        float4* dst = (float4*)w_s;
        #pragma unroll
        for (int i = 0; i < (N_EMB * EMB_D / 4) / TPB; i++)
            dst[i * TPB + tid] = src[i * TPB + tid];
        ww_s[tid]       = g_ww[tid];
        ww_s[tid + 256] = g_ww[tid + 256];
    }

    for (;;) {
        __syncthreads();
        if (tid == 0) s_chunk = (int)atomicAdd(&g_work, 1u);
        __syncthreads();
        int c = s_chunk;
        if (c >= NCHUNK) break;

        int t0 = c * TOKS_PER_CHUNK + tid;     // token A
        int t1 = t0 + TPB;                     // token B
        int b0 = t0 >> 12, hw0 = t0 & (HWSZ - 1);
        int b1 = t1 >> 12, hw1 = t1 & (HWSZ - 1);
        const float* xa_p = x + (size_t)b0 * EMB_D * HWSZ + hw0;
        const float* xb_p = x + (size_t)b1 * EMB_D * HWSZ + hw1;

        // Both tokens' features -> packed f32x2 registers
        unsigned long long xpa[EMB_D / 2];
        unsigned long long xpb[EMB_D / 2];
        #pragma unroll
        for (int i = 0; i < EMB_D / 2; i++) {
            xpa[i] = pack2(xa_p[(2 * i) * HWSZ], xa_p[(2 * i + 1) * HWSZ]);
            xpb[i] = pack2(xb_p[(2 * i) * HWSZ], xb_p[(2 * i + 1) * HWSZ]);
        }

        float bestA = 3.4e38f, bestB = 3.4e38f;
        int   biA = 0, biB = 0;

        #pragma unroll 1
        for (int j0 = 0; j0 < N_EMB; j0 += 2) {
            const ulonglong2* r0 = (const ulonglong2*)(w_s + (j0 + 0) * EMB_D);
            const ulonglong2* r1 = (const ulonglong2*)(w_s + (j0 + 1) * EMB_D);

            // accumulators: [codeword][token][even/odd half]
            unsigned long long a0Ae = 0ULL, a0Ao = 0ULL, a0Be = 0ULL, a0Bo = 0ULL;
            unsigned long long a1Ae = 0ULL, a1Ao = 0ULL, a1Be = 0ULL, a1Bo = 0ULL;

            #pragma unroll
            for (int q = 0; q < EMB_D / 4; q++) {
                ulonglong2 v0 = r0[q];     // broadcast LDS.128
                ulonglong2 v1 = r1[q];
                unsigned long long xaE = xpa[2 * q], xaO = xpa[2 * q + 1];
                unsigned long long xbE = xpb[2 * q], xbO = xpb[2 * q + 1];
                a0Ae = ffma2(xaE, v0.x, a0Ae);  a0Ao = ffma2(xaO, v0.y, a0Ao);
                a0Be = ffma2(xbE, v0.x, a0Be);  a0Bo = ffma2(xbO, v0.y, a0Bo);
                a1Ae = ffma2(xaE, v1.x, a1Ae);  a1Ao = ffma2(xaO, v1.y, a1Ao);
                a1Be = ffma2(xbE, v1.x, a1Be);  a1Bo = ffma2(xbO, v1.y, a1Bo);
            }

            float lo, hi;
            float w0 = ww_s[j0], w1 = ww_s[j0 + 1];
            unpack2(fadd2(a0Ae, a0Ao), lo, hi);
            float d0A = __fmaf_rn(-2.0f, __fadd_rn(lo, hi), w0);
            unpack2(fadd2(a1Ae, a1Ao), lo, hi);
            float d1A = __fmaf_rn(-2.0f, __fadd_rn(lo, hi), w1);
            unpack2(fadd2(a0Be, a0Bo), lo, hi);
            float d0B = __fmaf_rn(-2.0f, __fadd_rn(lo, hi), w0);
            unpack2(fadd2(a1Be, a1Bo), lo, hi);
            float d1B = __fmaf_rn(-2.0f, __fadd_rn(lo, hi), w1);

            // strict < ascending j => first-min tie-break (jnp.argmin)
            if (d0A < bestA) { bestA = d0A; biA = j0;     }
            if (d1A < bestA) { bestA = d1A; biA = j0 + 1; }
            if (d0B < bestB) { bestB = d0B; biB = j0;     }
            if (d1B < bestB) { bestB = d1B; biB = j0 + 1; }
        }

        out[OFF_ARG + (size_t)t0] = (float)biA;
        out[OFF_ARG + (size_t)t1] = (float)biB;

        // quantized result from smem codebook (coalesced per d-plane)
        {
            float* ro = out + (size_t)b0 * EMB_D * HWSZ + hw0;
            const float4* wrow = (const float4*)(w_s + biA * EMB_D);
            #pragma unroll
            for (int i = 0; i < EMB_D / 4; i++) {
                float4 v = wrow[i];
                ro[(4 * i + 0) * HWSZ] = v.x;
                ro[(4 * i + 1) * HWSZ] = v.y;
                ro[(4 * i + 2) * HWSZ] = v.z;
                ro[(4 * i + 3) * HWSZ] = v.w;
            }
        }
        {
            float* ro = out + (size_t)b1 * EMB_D * HWSZ + hw1;
            const float4* wrow = (const float4*)(w_s + biB * EMB_D);
            #pragma unroll
            for (int i = 0; i < EMB_D / 4; i++) {
                float4 v = wrow[i];
                ro[(4 * i + 0) * HWSZ] = v.x;
                ro[(4 * i + 1) * HWSZ] = v.y;
                ro[(4 * i + 2) * HWSZ] = v.z;
                ro[(4 * i + 3) * HWSZ] = v.w;
            }
        }

        // EMA accumulators
        atomicAdd(&g_hist[biA], 1.0f);
        atomicAdd(&g_hist[biB], 1.0f);
        #pragma unroll
        for (int i = 0; i < EMB_D / 2; i++) {
            float lo, hi;
            unpack2(xpa[i], lo, hi);
            atomicAdd(&g_esum[(2 * i)     * N_EMB + biA], lo);
            atomicAdd(&g_esum[(2 * i + 1) * N_EMB + biA], hi);
            unpack2(xpb[i], lo, hi);
            atomicAdd(&g_esum[(2 * i)     * N_EMB + biB], lo);
            atomicAdd(&g_esum[(2 * i + 1) * N_EMB + biB], hi);
        }
    }

    // ------- merged finalize: last CTA to finish does the EMA update -------
    __threadfence();
    __syncthreads();
    if (tid == 0) s_rank = atomicAdd(&g_done, 1u);
    __syncthreads();
    if (s_rank == GRID_A - 1) {
        float* red = smem_dyn;

        const float DEC  = 0.99f;
        const float OMD  = (float)(1.0 - 0.99);
        const float EPSF = (float)1e-5;
        const float NEPS = (float)(N_EMB * 1e-5);

        float ncs0, ncs1;
        {
            float n0 = g_hist[tid];
            if (n0 == 0.0f) n0 = 1.0f;
            ncs0 = __fadd_rn(__fmul_rn(DEC, cs_in[tid]), __fmul_rn(OMD, n0));
            float n1 = g_hist[tid + 256];
            if (n1 == 0.0f) n1 = 1.0f;
            ncs1 = __fadd_rn(__fmul_rn(DEC, cs_in[tid + 256]), __fmul_rn(OMD, n1));
        }

        __syncthreads();
        red[tid] = ncs0 + ncs1;
        __syncthreads();
        #pragma unroll
        for (int s = 128; s > 0; s >>= 1) {
            if (tid < s) red[tid] += red[tid + s];
            __syncthreads();
        }
        float n = red[0];

        float csn0 = __fmul_rn(__fdiv_rn(__fadd_rn(ncs0, EPSF),
                                         __fadd_rn(n, NEPS)), n);
        float csn1 = __fmul_rn(__fdiv_rn(__fadd_rn(ncs1, EPSF),
                                         __fadd_rn(n, NEPS)), n);

        out[OFF_CS + tid]       = ncs0;
        out[OFF_CS + tid + 256] = ncs1;

        for (int d = 0; d < EMB_D; d++) {
            int i0 = d * N_EMB + tid;
            int i1 = i0 + 256;
            float e0 = __fadd_rn(__fmul_rn(DEC, ea_in[i0]),
                                 __fmul_rn(OMD, g_esum[i0]));
            float e1 = __fadd_rn(__fmul_rn(DEC, ea_in[i1]),
                                 __fmul_rn(OMD, g_esum[i1]));
            out[OFF_EA + i0] = e0;
            out[OFF_EA + i1] = e1;
            out[OFF_W  + i0] = __fdiv_rn(e0, csn0);
            out[OFF_W  + i1] = __fdiv_rn(e1, csn1);
        }
    }
}

// ---------------------------------------------------------------------------
extern "C" void kernel_launch(void* const* d_in, const int* in_sizes, int n_in,
                              void* d_out, int out_size) {
    const float* x  = (const float*)d_in[0];
    const float* w  = (const float*)d_in[1];
    const float* cs = (const float*)d_in[2];
    const float* ea = (const float*)d_in[3];
    float* out = (float*)d_out;

    cudaFuncSetAttribute(assign_kernel,
                         cudaFuncAttributeMaxDynamicSharedMemorySize, SMEM_BYTES);

    prep_kernel<<<128, 256>>>(w);
    assign_kernel<<<GRID_A, TPB, SMEM_BYTES>>>(x, cs, ea, out);
}